// round 4
// baseline (speedup 1.0000x reference)
#include <cuda_runtime.h>
#include <cuda_bf16.h>
#include <math.h>
#include <stdint.h>

// GCN 2-layer: N=500000 nodes, E=8000000 edges, F=16 -> H=8 -> C=2
// Inputs (metadata order): x[N*16] f32, W1[16*8] f32, b1[8] f32,
//                          W2[8*2] f32, b2[2] f32, edge_index[2*E] i32
// Output: log_softmax [N*2] f32

#define MAXN 524288  // >= 500000, multiple of 4 for float4 init

// Scratch (static device globals — no allocation allowed)
__device__ __align__(16) float g_dinv[MAXN];        // deg, then rsqrt(deg)
__device__ __align__(16) float g_y1s [MAXN * 8];    // dinv * (x @ W1)
__device__ __align__(16) float g_agg1[MAXN * 8];    // layer-1 aggregation
__device__ __align__(16) float g_zs  [MAXN * 2];    // dinv * (h @ W2)

// ---------------------------------------------------------------------------
// no-return vectorized global reductions (sm_90+)
__device__ __forceinline__ void red_add_v4(float* addr, float a, float b, float c, float d) {
    asm volatile("red.global.add.v4.f32 [%0], {%1, %2, %3, %4};"
                 :: "l"(addr), "f"(a), "f"(b), "f"(c), "f"(d) : "memory");
}
__device__ __forceinline__ void red_add_v2(float* addr, float a, float b) {
    asm volatile("red.global.add.v2.f32 [%0], {%1, %2};"
                 :: "l"(addr), "f"(a), "f"(b) : "memory");
}
__device__ __forceinline__ void red_add_f32(float* addr, float a) {
    asm volatile("red.global.add.f32 [%0], %1;" :: "l"(addr), "f"(a) : "memory");
}

// ---------------------------------------------------------------------------
// K0: deg init to 1.0 (self-loop), vectorized. MAXN covers N; extra lanes harmless.
__global__ void k0_init_deg() {
    int i = blockIdx.x * blockDim.x + threadIdx.x;       // float4 index
    if (i < MAXN / 4)
        ((float4*)g_dinv)[i] = make_float4(1.f, 1.f, 1.f, 1.f);
}

// K1: in-degree count over col (8 edges / thread, int4 loads, REDG no-return)
__global__ void k1_degree(const int* __restrict__ col, int E, int vec_ok) {
    int base = (blockIdx.x * blockDim.x + threadIdx.x) * 8;
    if (vec_ok && base + 7 < E) {
        int4 c0 = __ldg((const int4*)(col + base));
        int4 c1 = __ldg((const int4*)(col + base + 4));
        red_add_f32(&g_dinv[c0.x], 1.0f);
        red_add_f32(&g_dinv[c0.y], 1.0f);
        red_add_f32(&g_dinv[c0.z], 1.0f);
        red_add_f32(&g_dinv[c0.w], 1.0f);
        red_add_f32(&g_dinv[c1.x], 1.0f);
        red_add_f32(&g_dinv[c1.y], 1.0f);
        red_add_f32(&g_dinv[c1.z], 1.0f);
        red_add_f32(&g_dinv[c1.w], 1.0f);
    } else {
        int end = base + 8; if (end > E) end = E;
        for (int e = base; e < end; e++) red_add_f32(&g_dinv[__ldg(col + e)], 1.0f);
    }
}

// K2: per-node — dinv = rsqrt(deg); y1s = dinv * (x @ W1); agg1 init = dinv * y1s
__global__ void k2_layer1_node(const float* __restrict__ x,
                               const float* __restrict__ W1, int N) {
    __shared__ float sW[128];  // 16x8
    if (threadIdx.x < 128) sW[threadIdx.x] = W1[threadIdx.x];
    __syncthreads();

    int i = blockIdx.x * blockDim.x + threadIdx.x;
    if (i >= N) return;

    float deg = g_dinv[i];              // holds degree here (>= 1 from self-loop)
    float dinv = rsqrtf(deg);
    g_dinv[i] = dinv;

    const float4* xp = (const float4*)(x + (size_t)i * 16);
    float4 x0 = xp[0], x1 = xp[1], x2 = xp[2], x3 = xp[3];
    float xi[16] = {x0.x,x0.y,x0.z,x0.w, x1.x,x1.y,x1.z,x1.w,
                    x2.x,x2.y,x2.z,x2.w, x3.x,x3.y,x3.z,x3.w};

    float y[8];
    #pragma unroll
    for (int j = 0; j < 8; j++) {
        float acc = 0.f;
        #pragma unroll
        for (int k = 0; k < 16; k++) acc = fmaf(xi[k], sW[k * 8 + j], acc);
        y[j] = acc;
    }

    float4 ya, yb, aa, ab;
    float* yav = &ya.x; float* ybv = &yb.x;
    float* aav = &aa.x; float* abv = &ab.x;
    #pragma unroll
    for (int j = 0; j < 4; j++) {
        float ys0 = dinv * y[j];
        float ys1 = dinv * y[j + 4];
        yav[j] = ys0;          ybv[j] = ys1;
        aav[j] = dinv * ys0;   abv[j] = dinv * ys1;   // self-loop term
    }
    ((float4*)(g_y1s  + (size_t)i * 8))[0] = ya;
    ((float4*)(g_y1s  + (size_t)i * 8))[1] = yb;
    ((float4*)(g_agg1 + (size_t)i * 8))[0] = aa;
    ((float4*)(g_agg1 + (size_t)i * 8))[1] = ab;
}

// K3: layer-1 edge scatter: agg1[c] += dinv[c] * y1s[r]
// 4 edges / thread. ALL loads (indices, dinv, payload gathers) are issued
// before the first RED: the "memory" clobber on red.* otherwise serializes
// each ~L2-latency gather behind the previous edge's atomic, collapsing MLP.
__global__ void k3_scatter1(const int* __restrict__ row,
                            const int* __restrict__ col, int E, int vec_ok) {
    int base = (blockIdx.x * blockDim.x + threadIdx.x) * 4;
    if (vec_ok && base + 3 < E) {
        int4 rv = __ldg((const int4*)(row + base));
        int4 cv = __ldg((const int4*)(col + base));
        int r[4] = {rv.x, rv.y, rv.z, rv.w};
        int c[4] = {cv.x, cv.y, cv.z, cv.w};
        float dc[4];
        float4 pa[4], pb[4];
        #pragma unroll
        for (int k = 0; k < 4; k++) dc[k] = __ldg(&g_dinv[c[k]]);
        #pragma unroll
        for (int k = 0; k < 4; k++) {
            const float4* yp = (const float4*)(g_y1s + (size_t)r[k] * 8);
            pa[k] = yp[0];
            pb[k] = yp[1];
        }
        // all 8 gathers + 4 dinv loads in flight; now drain into atomics
        #pragma unroll
        for (int k = 0; k < 4; k++) {
            float d = dc[k];
            float* dst = g_agg1 + (size_t)c[k] * 8;
            red_add_v4(dst,     d*pa[k].x, d*pa[k].y, d*pa[k].z, d*pa[k].w);
            red_add_v4(dst + 4, d*pb[k].x, d*pb[k].y, d*pb[k].z, d*pb[k].w);
        }
    } else {
        int end = base + 4; if (end > E) end = E;
        int cnt = end - base;
        int r[4], c[4];
        float dc[4];
        float4 pa[4], pb[4];
        for (int k = 0; k < cnt; k++) { r[k] = __ldg(row + base + k); c[k] = __ldg(col + base + k); }
        for (int k = 0; k < cnt; k++) dc[k] = __ldg(&g_dinv[c[k]]);
        for (int k = 0; k < cnt; k++) {
            const float4* yp = (const float4*)(g_y1s + (size_t)r[k] * 8);
            pa[k] = yp[0];
            pb[k] = yp[1];
        }
        for (int k = 0; k < cnt; k++) {
            float d = dc[k];
            float* dst = g_agg1 + (size_t)c[k] * 8;
            red_add_v4(dst,     d*pa[k].x, d*pa[k].y, d*pa[k].z, d*pa[k].w);
            red_add_v4(dst + 4, d*pb[k].x, d*pb[k].y, d*pb[k].z, d*pb[k].w);
        }
    }
}

// K4: per-node — h = relu(agg1 + b1); z = h @ W2; zs = dinv*z; d_out init = dinv*zs
__global__ void k4_layer2_node(const float* __restrict__ b1,
                               const float* __restrict__ W2,
                               float* __restrict__ out, int N) {
    __shared__ float sB[8];
    __shared__ float sW[16];
    if (threadIdx.x < 8)  sB[threadIdx.x] = b1[threadIdx.x];
    if (threadIdx.x >= 8 && threadIdx.x < 24) sW[threadIdx.x - 8] = W2[threadIdx.x - 8];
    __syncthreads();

    int i = blockIdx.x * blockDim.x + threadIdx.x;
    if (i >= N) return;

    float dinv = g_dinv[i];
    const float4* ap = (const float4*)(g_agg1 + (size_t)i * 8);
    float4 a = ap[0], b = ap[1];
    float h[8] = {a.x,a.y,a.z,a.w, b.x,b.y,b.z,b.w};
    float z0 = 0.f, z1 = 0.f;
    #pragma unroll
    for (int j = 0; j < 8; j++) {
        float hv = fmaxf(h[j] + sB[j], 0.0f);
        z0 = fmaf(hv, sW[j * 2 + 0], z0);
        z1 = fmaf(hv, sW[j * 2 + 1], z1);
    }
    float zs0 = dinv * z0, zs1 = dinv * z1;
    ((float2*)(g_zs + (size_t)i * 2))[0] = make_float2(zs0, zs1);
    ((float2*)(out  + (size_t)i * 2))[0] = make_float2(dinv * zs0, dinv * zs1); // self-loop
}

// K5: layer-2 edge scatter: out[c] += dinv[c] * zs[r]
// 8 edges / thread, int4 index loads, all loads batched before REDs
__global__ void k5_scatter2(const int* __restrict__ row,
                            const int* __restrict__ col,
                            float* __restrict__ out, int E, int vec_ok) {
    int base = (blockIdx.x * blockDim.x + threadIdx.x) * 8;
    if (vec_ok && base + 7 < E) {
        int4 r0 = __ldg((const int4*)(row + base));
        int4 r1 = __ldg((const int4*)(row + base + 4));
        int4 c0 = __ldg((const int4*)(col + base));
        int4 c1 = __ldg((const int4*)(col + base + 4));
        int r[8] = {r0.x,r0.y,r0.z,r0.w, r1.x,r1.y,r1.z,r1.w};
        int c[8] = {c0.x,c0.y,c0.z,c0.w, c1.x,c1.y,c1.z,c1.w};
        float2 z[8]; float d[8];
        #pragma unroll
        for (int k = 0; k < 8; k++) {
            d[k] = __ldg(&g_dinv[c[k]]);
            z[k] = *((const float2*)(g_zs + (size_t)r[k] * 2));
        }
        #pragma unroll
        for (int k = 0; k < 8; k++)
            red_add_v2(out + (size_t)c[k] * 2, d[k] * z[k].x, d[k] * z[k].y);
    } else {
        int end = base + 8; if (end > E) end = E;
        for (int e = base; e < end; e++) {
            int rr = __ldg(row + e), cc = __ldg(col + e);
            float dd = __ldg(&g_dinv[cc]);
            float2 zz = *((const float2*)(g_zs + (size_t)rr * 2));
            red_add_v2(out + (size_t)cc * 2, dd * zz.x, dd * zz.y);
        }
    }
}

// K6: out = log_softmax(out + b2), in place, 2 classes
__global__ void k6_finalize(const float* __restrict__ b2,
                            float* __restrict__ out, int N) {
    int i = blockIdx.x * blockDim.x + threadIdx.x;
    if (i >= N) return;
    float b20 = __ldg(b2 + 0), b21 = __ldg(b2 + 1);
    float2 v = ((float2*)(out + (size_t)i * 2))[0];
    float v0 = v.x + b20, v1 = v.y + b21;
    float m = fmaxf(v0, v1);
    float lse = m + logf(expf(v0 - m) + expf(v1 - m));
    ((float2*)(out + (size_t)i * 2))[0] = make_float2(v0 - lse, v1 - lse);
}

// ---------------------------------------------------------------------------
extern "C" void kernel_launch(void* const* d_in, const int* in_sizes, int n_in,
                              void* d_out, int out_size) {
    const float* x   = (const float*)d_in[0];
    const float* W1  = (const float*)d_in[1];
    const float* b1  = (const float*)d_in[2];
    const float* W2  = (const float*)d_in[3];
    const float* b2  = (const float*)d_in[4];
    const int*   ei  = (const int*)d_in[5];

    int N = in_sizes[0] / 16;
    int E = in_sizes[5] / 2;
    const int* row = ei;
    const int* col = ei + E;

    // int4 fast path requires both halves 16B-aligned
    int vec_ok = (((uintptr_t)row & 15) == 0) && (((uintptr_t)col & 15) == 0);

    float* out = (float*)d_out;

    const int T = 256;
    int nb_node  = (N + T - 1) / T;
    int nb_init  = (MAXN / 4 + T - 1) / T;
    int nb_edge4 = ((E + 3) / 4 + T - 1) / T;
    int nb_edge8 = ((E + 7) / 8 + T - 1) / T;

    k0_init_deg   <<<nb_init, T>>>();
    k1_degree     <<<nb_edge8, T>>>(col, E, vec_ok);
    k2_layer1_node<<<nb_node, T>>>(x, W1, N);
    k3_scatter1   <<<nb_edge4, T>>>(row, col, E, vec_ok);
    k4_layer2_node<<<nb_node, T>>>(b1, W2, out, N);
    k5_scatter2   <<<nb_edge8, T>>>(row, col, out, E, vec_ok);
    k6_finalize   <<<nb_node, T>>>(b2, out, N);
}

// round 10
// speedup vs baseline: 1.1723x; 1.1723x over previous
#include <cuda_runtime.h>
#include <cuda_bf16.h>
#include <math.h>
#include <stdint.h>

// GCN 2-layer: N=500000 nodes, E=8000000 edges, F=16 -> H=8 -> C=2
// agg[c] = dinv[c] * ( sum_r y1s[r] + y1s[c] ),  y1s[r] = dinv[r]*(xW1)[r]
// -> edge kernels do PLAIN adds (no dinv[c] gather, no per-edge multiply);
//    the dinv[c] scale is applied at node level (K4 / K6).

#define MAXN 524288  // >= 500000, multiple of 4 for float4 init

__device__ __align__(16) float g_dinv[MAXN];        // deg, then rsqrt(deg)
__device__ __align__(16) float g_y1s [MAXN * 8];    // dinv * (x @ W1)
__device__ __align__(16) float g_agg1[MAXN * 8];    // unscaled layer-1 aggregation
__device__ __align__(16) float g_zs  [MAXN * 2];    // dinv * (h @ W2)

// ---------------------------------------------------------------------------
// no-return vectorized global reductions (sm_90+)
__device__ __forceinline__ void red_add_v4(float* addr, float a, float b, float c, float d) {
    asm volatile("red.global.add.v4.f32 [%0], {%1, %2, %3, %4};"
                 :: "l"(addr), "f"(a), "f"(b), "f"(c), "f"(d) : "memory");
}
__device__ __forceinline__ void red_add_v2(float* addr, float a, float b) {
    asm volatile("red.global.add.v2.f32 [%0], {%1, %2};"
                 :: "l"(addr), "f"(a), "f"(b) : "memory");
}
__device__ __forceinline__ void red_add_f32(float* addr, float a) {
    asm volatile("red.global.add.f32 [%0], %1;" :: "l"(addr), "f"(a) : "memory");
}

// ---------------------------------------------------------------------------
// K0: deg init to 1.0 (self-loop), vectorized.
__global__ void k0_init_deg() {
    int i = blockIdx.x * blockDim.x + threadIdx.x;       // float4 index
    if (i < MAXN / 4)
        ((float4*)g_dinv)[i] = make_float4(1.f, 1.f, 1.f, 1.f);
}

// K1: in-degree count over col (16 edges / thread, int4 loads, REDG no-return)
__global__ void k1_degree(const int* __restrict__ col, int E, int vec_ok) {
    int base = (blockIdx.x * blockDim.x + threadIdx.x) * 16;
    if (vec_ok && base + 15 < E) {
        int4 cv[4];
        #pragma unroll
        for (int q = 0; q < 4; q++) cv[q] = __ldg((const int4*)(col + base + q * 4));
        #pragma unroll
        for (int q = 0; q < 4; q++) {
            red_add_f32(&g_dinv[cv[q].x], 1.0f);
            red_add_f32(&g_dinv[cv[q].y], 1.0f);
            red_add_f32(&g_dinv[cv[q].z], 1.0f);
            red_add_f32(&g_dinv[cv[q].w], 1.0f);
        }
    } else {
        int end = base + 16; if (end > E) end = E;
        for (int e = base; e < end; e++) red_add_f32(&g_dinv[__ldg(col + e)], 1.0f);
    }
}

// K2: per-node — dinv = rsqrt(deg); y1s = dinv * (x @ W1); agg1 init = y1s (self-loop inner term)
__global__ void k2_layer1_node(const float* __restrict__ x,
                               const float* __restrict__ W1, int N) {
    __shared__ float sW[128];  // 16x8
    if (threadIdx.x < 128) sW[threadIdx.x] = W1[threadIdx.x];
    __syncthreads();

    int i = blockIdx.x * blockDim.x + threadIdx.x;
    if (i >= N) return;

    float deg = g_dinv[i];              // holds degree here (>= 1 from self-loop)
    float dinv = rsqrtf(deg);
    g_dinv[i] = dinv;

    const float4* xp = (const float4*)(x + (size_t)i * 16);
    float4 x0 = xp[0], x1 = xp[1], x2 = xp[2], x3 = xp[3];
    float xi[16] = {x0.x,x0.y,x0.z,x0.w, x1.x,x1.y,x1.z,x1.w,
                    x2.x,x2.y,x2.z,x2.w, x3.x,x3.y,x3.z,x3.w};

    float y[8];
    #pragma unroll
    for (int j = 0; j < 8; j++) {
        float acc = 0.f;
        #pragma unroll
        for (int k = 0; k < 16; k++) acc = fmaf(xi[k], sW[k * 8 + j], acc);
        y[j] = acc;
    }

    float4 ya, yb;
    float* yav = &ya.x; float* ybv = &yb.x;
    #pragma unroll
    for (int j = 0; j < 4; j++) {
        yav[j] = dinv * y[j];
        ybv[j] = dinv * y[j + 4];
    }
    ((float4*)(g_y1s  + (size_t)i * 8))[0] = ya;
    ((float4*)(g_y1s  + (size_t)i * 8))[1] = yb;
    ((float4*)(g_agg1 + (size_t)i * 8))[0] = ya;   // self-loop inner term
    ((float4*)(g_agg1 + (size_t)i * 8))[1] = yb;
}

// K3: layer-1 edge scatter: agg1[c] += y1s[r]  (plain add, no dinv gather)
// 4 edges / thread; all loads issued before the first RED (memory clobber
// would otherwise serialize gathers behind atomics).
__global__ void k3_scatter1(const int* __restrict__ row,
                            const int* __restrict__ col, int E, int vec_ok) {
    int base = (blockIdx.x * blockDim.x + threadIdx.x) * 4;
    if (vec_ok && base + 3 < E) {
        int4 rv = __ldg((const int4*)(row + base));
        int4 cv = __ldg((const int4*)(col + base));
        int r[4] = {rv.x, rv.y, rv.z, rv.w};
        int c[4] = {cv.x, cv.y, cv.z, cv.w};
        float4 pa[4], pb[4];
        #pragma unroll
        for (int k = 0; k < 4; k++) {
            const float4* yp = (const float4*)(g_y1s + (size_t)r[k] * 8);
            pa[k] = yp[0];
            pb[k] = yp[1];
        }
        #pragma unroll
        for (int k = 0; k < 4; k++) {
            float* dst = g_agg1 + (size_t)c[k] * 8;
            red_add_v4(dst,     pa[k].x, pa[k].y, pa[k].z, pa[k].w);
            red_add_v4(dst + 4, pb[k].x, pb[k].y, pb[k].z, pb[k].w);
        }
    } else {
        int end = base + 4; if (end > E) end = E;
        int cnt = end - base;
        int r[4], c[4];
        float4 pa[4], pb[4];
        for (int k = 0; k < cnt; k++) { r[k] = __ldg(row + base + k); c[k] = __ldg(col + base + k); }
        for (int k = 0; k < cnt; k++) {
            const float4* yp = (const float4*)(g_y1s + (size_t)r[k] * 8);
            pa[k] = yp[0];
            pb[k] = yp[1];
        }
        for (int k = 0; k < cnt; k++) {
            float* dst = g_agg1 + (size_t)c[k] * 8;
            red_add_v4(dst,     pa[k].x, pa[k].y, pa[k].z, pa[k].w);
            red_add_v4(dst + 4, pb[k].x, pb[k].y, pb[k].z, pb[k].w);
        }
    }
}

// K4: per-node — h = relu(dinv*agg1 + b1); z = h @ W2; zs = dinv*z; out init = zs
__global__ void k4_layer2_node(const float* __restrict__ b1,
                               const float* __restrict__ W2,
                               float* __restrict__ out, int N) {
    __shared__ float sB[8];
    __shared__ float sW[16];
    if (threadIdx.x < 8)  sB[threadIdx.x] = b1[threadIdx.x];
    if (threadIdx.x >= 8 && threadIdx.x < 24) sW[threadIdx.x - 8] = W2[threadIdx.x - 8];
    __syncthreads();

    int i = blockIdx.x * blockDim.x + threadIdx.x;
    if (i >= N) return;

    float dinv = g_dinv[i];
    const float4* ap = (const float4*)(g_agg1 + (size_t)i * 8);
    float4 a = ap[0], b = ap[1];
    float h[8] = {a.x,a.y,a.z,a.w, b.x,b.y,b.z,b.w};
    float z0 = 0.f, z1 = 0.f;
    #pragma unroll
    for (int j = 0; j < 8; j++) {
        float hv = fmaxf(fmaf(dinv, h[j], sB[j]), 0.0f);   // dinv*agg + b1
        z0 = fmaf(hv, sW[j * 2 + 0], z0);
        z1 = fmaf(hv, sW[j * 2 + 1], z1);
    }
    float zs0 = dinv * z0, zs1 = dinv * z1;
    ((float2*)(g_zs + (size_t)i * 2))[0] = make_float2(zs0, zs1);
    ((float2*)(out  + (size_t)i * 2))[0] = make_float2(zs0, zs1);  // self-loop inner term
}

// K5: layer-2 edge scatter: out[c] += zs[r]  (plain add, no dinv gather)
__global__ void k5_scatter2(const int* __restrict__ row,
                            const int* __restrict__ col,
                            float* __restrict__ out, int E, int vec_ok) {
    int base = (blockIdx.x * blockDim.x + threadIdx.x) * 8;
    if (vec_ok && base + 7 < E) {
        int4 r0 = __ldg((const int4*)(row + base));
        int4 r1 = __ldg((const int4*)(row + base + 4));
        int4 c0 = __ldg((const int4*)(col + base));
        int4 c1 = __ldg((const int4*)(col + base + 4));
        int r[8] = {r0.x,r0.y,r0.z,r0.w, r1.x,r1.y,r1.z,r1.w};
        int c[8] = {c0.x,c0.y,c0.z,c0.w, c1.x,c1.y,c1.z,c1.w};
        float2 z[8];
        #pragma unroll
        for (int k = 0; k < 8; k++)
            z[k] = *((const float2*)(g_zs + (size_t)r[k] * 2));
        #pragma unroll
        for (int k = 0; k < 8; k++)
            red_add_v2(out + (size_t)c[k] * 2, z[k].x, z[k].y);
    } else {
        int end = base + 8; if (end > E) end = E;
        for (int e = base; e < end; e++) {
            int rr = __ldg(row + e), cc = __ldg(col + e);
            float2 zz = *((const float2*)(g_zs + (size_t)rr * 2));
            red_add_v2(out + (size_t)cc * 2, zz.x, zz.y);
        }
    }
}

// K6: out = log_softmax(dinv*out + b2), in place, 2 classes
__global__ void k6_finalize(const float* __restrict__ b2,
                            float* __restrict__ out, int N) {
    int i = blockIdx.x * blockDim.x + threadIdx.x;
    if (i >= N) return;
    float b20 = __ldg(b2 + 0), b21 = __ldg(b2 + 1);
    float dinv = g_dinv[i];
    float2 v = ((float2*)(out + (size_t)i * 2))[0];
    float v0 = fmaf(dinv, v.x, b20), v1 = fmaf(dinv, v.y, b21);
    float m = fmaxf(v0, v1);
    float lse = m + logf(expf(v0 - m) + expf(v1 - m));
    ((float2*)(out + (size_t)i * 2))[0] = make_float2(v0 - lse, v1 - lse);
}

// ---------------------------------------------------------------------------
extern "C" void kernel_launch(void* const* d_in, const int* in_sizes, int n_in,
                              void* d_out, int out_size) {
    const float* x   = (const float*)d_in[0];
    const float* W1  = (const float*)d_in[1];
    const float* b1  = (const float*)d_in[2];
    const float* W2  = (const float*)d_in[3];
    const float* b2  = (const float*)d_in[4];
    const int*   ei  = (const int*)d_in[5];

    int N = in_sizes[0] / 16;
    int E = in_sizes[5] / 2;
    const int* row = ei;
    const int* col = ei + E;

    int vec_ok = (((uintptr_t)row & 15) == 0) && (((uintptr_t)col & 15) == 0);

    float* out = (float*)d_out;

    const int T = 256;
    int nb_node   = (N + T - 1) / T;
    int nb_init   = (MAXN / 4 + T - 1) / T;
    int nb_edge4  = ((E + 3) / 4 + T - 1) / T;
    int nb_edge8  = ((E + 7) / 8 + T - 1) / T;
    int nb_edge16 = ((E + 15) / 16 + T - 1) / T;

    k0_init_deg   <<<nb_init, T>>>();
    k1_degree     <<<nb_edge16, T>>>(col, E, vec_ok);
    k2_layer1_node<<<nb_node, T>>>(x, W1, N);
    k3_scatter1   <<<nb_edge4, T>>>(row, col, E, vec_ok);
    k4_layer2_node<<<nb_node, T>>>(b1, W2, out, N);
    k5_scatter2   <<<nb_edge8, T>>>(row, col, out, E, vec_ok);
    k6_finalize   <<<nb_node, T>>>(b2, out, N);
}